// round 15
// baseline (speedup 1.0000x reference)
#include <cuda_runtime.h>
#include <cuda_fp16.h>
#include <math.h>
#include <stdint.h>

#define B_   16384
#define D_   256
#define ML_  10
#define M2_  (B_*9)

typedef __half h16;

// ---------------- fp16 scratch ----------------
__device__ __align__(256) h16 g_QK   [(size_t)B_*256];
__device__ __align__(256) h16 g_gates[(size_t)B_*768];
__device__ __align__(256) h16 g_OZH  [(size_t)B_*768];
__device__ __align__(256) h16 g_X   [(size_t)B_*512];
__device__ __align__(256) h16 g_OTP [(size_t)B_*256];
__device__ __align__(256) h16 g_WM  [(size_t)B_*256];
__device__ __align__(256) h16 g_MEMh[(size_t)B_*ML_*256];
// ---------------- fp16 weights ----------------
__device__ __align__(256) h16 g_Wigo [768*512];
__device__ __align__(256) h16 g_Wqk  [65536];
__device__ __align__(256) h16 g_Wvoz [1024*256];   // rows 0-255: Wv ; rows 256-1023: Wozh@Wv
__device__ __align__(256) h16 g_Wzrm [512*256];
__device__ __align__(256) h16 g_Whm  [256*256];
__device__ __align__(256) float g_bigo[768];
__device__ __align__(256) float g_bvoz[1024];      // [vb ; bozh + Wozh@vb]
__device__ __align__(256) float g_bqk [256];

__device__ __forceinline__ float sigf(float x){ return 1.f/(1.f+expf(-x)); }

// ---------------- PTX helpers (base ISA only) ----------------
__device__ __forceinline__ uint32_t smem_u32(const void* p){
    uint32_t a; asm("{ .reg .u64 t; cvta.to.shared.u64 t, %1; cvt.u32.u64 %0, t; }" : "=r"(a) : "l"(p));
    return a;
}
__device__ __forceinline__ void ldsm4(uint32_t* r, uint32_t addr){
    asm volatile("ldmatrix.sync.aligned.m8n8.x4.shared.b16 {%0,%1,%2,%3}, [%4];"
        : "=r"(r[0]),"=r"(r[1]),"=r"(r[2]),"=r"(r[3]) : "r"(addr));
}
__device__ __forceinline__ void mma_f16(float* c, const uint32_t* a, const uint32_t* b){
    asm volatile("mma.sync.aligned.m16n8k16.row.col.f32.f16.f16.f32 "
        "{%0,%1,%2,%3}, {%4,%5,%6,%7}, {%8,%9}, {%0,%1,%2,%3};"
        : "+f"(c[0]),"+f"(c[1]),"+f"(c[2]),"+f"(c[3])
        : "r"(a[0]),"r"(a[1]),"r"(a[2]),"r"(a[3]), "r"(b[0]),"r"(b[1]));
}
__device__ __forceinline__ void cpa16(uint32_t dst, const void* src){
    asm volatile("cp.async.cg.shared.global [%0], [%1], 16;" :: "r"(dst), "l"(src));
}
#define CP_COMMIT() asm volatile("cp.async.commit_group;" ::: "memory")
#define CP_WAIT1()  asm volatile("cp.async.wait_group 1;"  ::: "memory")
#define CP_WAIT0()  asm volatile("cp.async.wait_group 0;"  ::: "memory")

#define ROWB     144
#define STAGE_SZ 36864
#define SMEM_TOTAL (3*STAGE_SZ)

// ================== fp16 HMMA GEMM: C[M,N] = A[M,K] @ W[N,K]^T ==================
// CTA 128x128, 8 warps (2x4), warp tile 64x32, K-chunk 64, 3-stage cp.async, 2 CTAs/SM.
// EPI 5: C16 fp16 = v + bias[col]
// EPI 6: merged V/OZH: col<256 -> v(+bias) fp32 to out0/out2/out_mem slot9;
//        col>=256 -> fp16 OZH[rr*768 + col-256]
template<int EPI>
__global__ void __launch_bounds__(256,2) k_mma(
    const h16* __restrict__ A,
    const h16* __restrict__ W,
    const float* __restrict__ bias,
    h16* __restrict__ C16,
    float* __restrict__ out0, float* __restrict__ out_mem, float* __restrict__ out2,
    int M, int N, int K)
{
    extern __shared__ char smem[];
    uint32_t sb = smem_u32(smem);
    const int tid = threadIdx.x, lane = tid & 31, w = tid >> 5;
    const int wm = w >> 2, wn = w & 3;
    const int m0 = blockIdx.y * 128, n0 = blockIdx.x * 128;
    const int nch = K >> 6;

    float acc[4][4][4];
    #pragma unroll
    for (int i=0;i<4;i++)
        #pragma unroll
        for (int j=0;j<4;j++)
            #pragma unroll
            for (int k=0;k<4;k++) acc[i][j][k]=0.f;

    auto load_chunk = [&](int c, int s){
        uint32_t st = sb + s*STAGE_SZ;
        #pragma unroll
        for (int t=0;t<4;t++){
            int u = tid + t*256;
            int row = u >> 3, q = u & 7;
            cpa16(st + row*ROWB + q*16, A + (size_t)(m0+row)*K + c*64 + q*8);
        }
        #pragma unroll
        for (int t=0;t<4;t++){
            int u = tid + t*256;
            int row = u >> 3, q = u & 7;
            cpa16(st + 18432 + row*ROWB + q*16, W + (size_t)(n0+row)*K + c*64 + q*8);
        }
        CP_COMMIT();
    };

    load_chunk(0, 0);
    load_chunk(1, 1);

    for (int c = 0; c < nch; c++){
        if (c == nch - 1) CP_WAIT0(); else CP_WAIT1();
        __syncthreads();
        if (c + 2 < nch) load_chunk(c + 2, (c + 2) % 3);

        uint32_t sA = sb + (c % 3)*STAGE_SZ;
        uint32_t sW = sA + 18432;
        #pragma unroll
        for (int kk = 0; kk < 4; kk++){
            uint32_t a[4][4];
            #pragma unroll
            for (int i = 0; i < 4; i++){
                int rl = wm*64 + i*16 + (lane & 7) + ((lane & 8) ? 8 : 0);
                uint32_t colb = kk*32 + ((lane & 16) ? 16 : 0);
                ldsm4(a[i], sA + rl*ROWB + colb);
            }
            uint32_t bf[4][2];
            #pragma unroll
            for (int jp = 0; jp < 2; jp++){
                int nl = wn*32 + jp*16 + (lane & 7) + ((lane & 16) ? 8 : 0);
                uint32_t colb = kk*32 + ((lane & 8) ? 16 : 0);
                uint32_t t4[4];
                ldsm4(t4, sW + nl*ROWB + colb);
                bf[2*jp][0]=t4[0]; bf[2*jp][1]=t4[1]; bf[2*jp+1][0]=t4[2]; bf[2*jp+1][1]=t4[3];
            }
            #pragma unroll
            for (int i=0;i<4;i++)
                #pragma unroll
                for (int j=0;j<4;j++) mma_f16(acc[i][j], a[i], bf[j]);
        }
        __syncthreads();
    }

    #pragma unroll
    for (int j = 0; j < 4; j++){
        int col = n0 + wn*32 + j*8 + (lane & 3)*2;
        float b0 = bias ? bias[col]   : 0.f;
        float b1 = bias ? bias[col+1] : 0.f;
        #pragma unroll
        for (int i = 0; i < 4; i++){
            int row = m0 + wm*64 + i*16 + (lane >> 2);
            #pragma unroll
            for (int h = 0; h < 2; h++){
                int rr = row + h*8;
                float v0 = acc[i][j][2*h+0] + b0;
                float v1 = acc[i][j][2*h+1] + b1;
                if (EPI == 5){
                    *reinterpret_cast<__half2*>(C16 + (size_t)rr*N + col) = __floats2half2_rn(v0, v1);
                } else {  // EPI 6
                    if (col < 256){
                        size_t o = (size_t)rr*256 + col;
                        float2 fv = make_float2(v0, v1);
                        *reinterpret_cast<float2*>(out0 + o) = fv;
                        *reinterpret_cast<float2*>(out2 + o) = fv;
                        *reinterpret_cast<float2*>(out_mem + (size_t)rr*(ML_*256) + 9*256 + col) = fv;
                    } else {
                        *reinterpret_cast<__half2*>(C16 + (size_t)rr*768 + (col - 256)) =
                            __floats2half2_rn(v0, v1);
                    }
                }
            }
        }
    }
}

// ================== fused GRU v3: 64-row CTAs, 2 CTAs/SM ==================
#define GRU_ROWSTR 528
#define GRU_A_OFF  0
#define GRU_RM_OFF 33792
#define GRU_ZS_OFF 67584
#define GRU_W_OFF  83968
#define GRU_WSTG   10240
#define GRU_SMEM   104448

__device__ __forceinline__ uint32_t zswz(int rl, int ccl){
    return (uint32_t)((rl*256 + ccl*2) ^ ((rl & 7) << 4));
}

__global__ void __launch_bounds__(256,2) k_gru(
    const h16* __restrict__ memh,
    const h16* __restrict__ Wzrm, const h16* __restrict__ Whm,
    const h16* __restrict__ ozh,
    float* __restrict__ out_mem)
{
    extern __shared__ char smem[];
    uint32_t sb = smem_u32(smem);
    const int tid = threadIdx.x, lane = tid & 31, w = tid >> 5;
    const int wm = w >> 2, wn = w & 3;
    const int m0 = blockIdx.x * 64;

    #pragma unroll
    for (int t = 0; t < 8; t++){
        int u = tid + t*256;
        int row = u >> 5, q = u & 31;
        int rr = m0 + row, b = rr/9, m = rr - b*9 + 1;
        cpa16(sb + GRU_A_OFF + row*GRU_ROWSTR + q*16,
              memh + ((size_t)b*10 + m)*256 + q*8);
    }
    CP_COMMIT(); CP_WAIT0(); __syncthreads();

    auto wptr = [&](int p)->const h16*{
        switch(p){
            case 0: return Wzrm;
            case 1: return Wzrm + 256*256;
            case 2: return Wzrm + 384*256;
            case 3: return Whm;
            case 4: return Wzrm + 128*256;
            default:return Whm + 128*256;
        }
    };
    auto wload = [&](const h16* Wg, int c, int s){
        #pragma unroll
        for (int t = 0; t < 2; t++){
            int u = tid + t*256;
            int row = u >> 2, q = u & 3;
            cpa16(sb + GRU_W_OFF + s*GRU_WSTG + row*80 + q*16,
                  Wg + (size_t)row*256 + c*32 + q*8);
        }
        CP_COMMIT();
    };

    wload(wptr(0), 0, 0);
    wload(wptr(0), 1, 1);

    for (int pass = 0; pass < 6; pass++){
        const h16* Wg;
        uint32_t aOff; int colOff, mode;
        switch(pass){
            case 0: Wg=wptr(0); aOff=GRU_A_OFF;  colOff=0;   mode=0; break;
            case 1: Wg=wptr(1); aOff=GRU_A_OFF;  colOff=0;   mode=1; break;
            case 2: Wg=wptr(2); aOff=GRU_A_OFF;  colOff=128; mode=1; break;
            case 3: Wg=wptr(3); aOff=GRU_RM_OFF; colOff=0;   mode=2; break;
            case 4: Wg=wptr(4); aOff=GRU_A_OFF;  colOff=128; mode=0; break;
            default:Wg=wptr(5); aOff=GRU_RM_OFF; colOff=128; mode=2; break;
        }
        uint32_t aBase = sb + aOff;

        float acc[2][4][4];
        #pragma unroll
        for (int i=0;i<2;i++)
            #pragma unroll
            for (int j=0;j<4;j++)
                #pragma unroll
                for (int k=0;k<4;k++) acc[i][j][k]=0.f;

        for (int c = 0; c < 8; c++){
            if (c == 7) CP_WAIT0(); else CP_WAIT1();
            __syncthreads();
            uint32_t sW = sb + GRU_W_OFF + (c & 1)*GRU_WSTG;
            #pragma unroll
            for (int s = 0; s < 2; s++){
                int kg = c*2 + s;
                uint32_t a[2][4];
                #pragma unroll
                for (int i = 0; i < 2; i++){
                    int rl = wm*32 + i*16 + (lane & 7) + ((lane & 8) ? 8 : 0);
                    uint32_t colb = kg*32 + ((lane & 16) ? 16 : 0);
                    ldsm4(a[i], aBase + rl*GRU_ROWSTR + colb);
                }
                uint32_t bf[4][2];
                #pragma unroll
                for (int jp = 0; jp < 2; jp++){
                    int nl = wn*32 + jp*16 + (lane & 7) + ((lane & 16) ? 8 : 0);
                    uint32_t colb = s*32 + ((lane & 8) ? 16 : 0);
                    uint32_t t4[4];
                    ldsm4(t4, sW + nl*80 + colb);
                    bf[2*jp][0]=t4[0]; bf[2*jp][1]=t4[1]; bf[2*jp+1][0]=t4[2]; bf[2*jp+1][1]=t4[3];
                }
                #pragma unroll
                for (int i=0;i<2;i++)
                    #pragma unroll
                    for (int j=0;j<4;j++) mma_f16(acc[i][j], a[i], bf[j]);
            }
            __syncthreads();
            if (c + 2 < 8) wload(Wg, c + 2, c & 1);
        }

        if (pass < 5){
            const h16* Wn = wptr(pass + 1);
            wload(Wn, 0, 0);
            wload(Wn, 1, 1);
        }

        #pragma unroll
        for (int j = 0; j < 4; j++){
            int ccl = wn*32 + j*8 + (lane & 3)*2;
            int cc  = colOff + ccl;
            #pragma unroll
            for (int i = 0; i < 2; i++){
                #pragma unroll
                for (int h = 0; h < 2; h++){
                    int rl = wm*32 + i*16 + (lane >> 2) + h*8;
                    int rr = m0 + rl, b = rr/9;
                    float v0 = acc[i][j][2*h], v1 = acc[i][j][2*h+1];
                    if (mode == 0){
                        float2 oz = __half22float2(*reinterpret_cast<const __half2*>(ozh + (size_t)b*768 + cc));
                        *reinterpret_cast<__half2*>(smem + GRU_ZS_OFF + zswz(rl, ccl)) =
                            __floats2half2_rn(sigf(v0+oz.x), sigf(v1+oz.y));
                    } else if (mode == 1){
                        float2 oz = __half22float2(*reinterpret_cast<const __half2*>(ozh + (size_t)b*768 + 256 + cc));
                        float2 mv = __half22float2(*reinterpret_cast<const __half2*>(smem + GRU_A_OFF + rl*GRU_ROWSTR + cc*2));
                        *reinterpret_cast<__half2*>(smem + GRU_RM_OFF + rl*GRU_ROWSTR + cc*2) =
                            __floats2half2_rn(sigf(v0+oz.x)*mv.x, sigf(v1+oz.y)*mv.y);
                    } else {
                        int m = rr - b*9 + 1;
                        float2 oz = __half22float2(*reinterpret_cast<const __half2*>(ozh + (size_t)b*768 + 512 + cc));
                        float mt0 = tanhf(v0+oz.x), mt1 = tanhf(v1+oz.y);
                        float2 zv = __half22float2(*reinterpret_cast<const __half2*>(smem + GRU_ZS_OFF + zswz(rl, ccl)));
                        float2 mv = __half22float2(*reinterpret_cast<const __half2*>(smem + GRU_A_OFF + rl*GRU_ROWSTR + cc*2));
                        *reinterpret_cast<float2*>(out_mem + (size_t)b*(ML_*256) + (size_t)(m-1)*256 + cc) =
                            make_float2(zv.x*mv.x + (1.f-zv.x)*mt0, zv.y*mv.y + (1.f-zv.y)*mt1);
                    }
                }
            }
        }
        __syncthreads();
    }
}

// ---------------- fused front launch ----------------
#define PB_QK    256
#define PB_BIAS  4
#define PB_WIGO  1536
#define PB_WZRM  512
#define PB_WHM   256
#define PB_WVOZ  768
#define PB_WV    256
#define PB_MEMC  20480
#define PB_FRAME 16384
#define PB_TOTAL (PB_QK+PB_BIAS+PB_WIGO+PB_WZRM+PB_WHM+PB_WVOZ+PB_WV+PB_MEMC+PB_FRAME)

__global__ void k_prep_all(const float* __restrict__ qW, const float* __restrict__ kW,
                           const float* __restrict__ qb,
                           const float* __restrict__ Wih,
                           const float* __restrict__ bih, const float* __restrict__ bhh,
                           const float* __restrict__ vW, const float* __restrict__ vb,
                           const float* __restrict__ zW, const float* __restrict__ rW,
                           const float* __restrict__ hW,
                           const float* __restrict__ zb, const float* __restrict__ rb,
                           const float* __restrict__ hb,
                           const float* __restrict__ memory,
                           const float* __restrict__ O_t, const float* __restrict__ O_prev,
                           const float* __restrict__ wW, const float* __restrict__ wb,
                           float* __restrict__ out_Wt)
{
    int blk = blockIdx.x;
    if (blk < PB_QK){
        int j = blk, e = threadIdx.x;
        float s = 0.f;
        for (int d = 0; d < 256; d++) s = fmaf(qW[d*256 + e], kW[d*256 + j], s);
        g_Wqk[j*256 + e] = __float2half_rn(s);
        if (e == 0){
            float bq = 0.f;
            for (int d = 0; d < 256; d++) bq = fmaf(qb[d], kW[d*256 + j], bq);
            g_bqk[j] = bq;
        }
        return;
    } blk -= PB_QK;
    if (blk < PB_BIAS){
        int i = blk*256 + threadIdx.x;
        if (i < 768){
            int src = (i < 256) ? i : i + 256;
            g_bigo[i] = bih[src] + bhh[src];
        } else if (i < 1024){
            g_bvoz[i - 768] = vb[i - 768];   // V-half bias
        }
        return;
    } blk -= PB_BIAS;
    if (blk < PB_WIGO){
        int i = blk*256 + threadIdx.x;
        int n = i >> 9, k = i & 511;
        int src = (n < 256) ? n : n + 256;
        g_Wigo[i] = __float2half_rn(Wih[(size_t)src*512 + k]);
        return;
    } blk -= PB_WIGO;
    if (blk < PB_WZRM){
        int i = blk*256 + threadIdx.x;
        int n = i >> 8, k = i & 255;
        float v = (n < 256) ? zW[(size_t)n*512 + k] : rW[(size_t)(n-256)*512 + k];
        g_Wzrm[i] = __float2half_rn(v);
        return;
    } blk -= PB_WZRM;
    if (blk < PB_WHM){
        int i = blk*256 + threadIdx.x;
        int n = i >> 8, k = i & 255;
        g_Whm[i] = __float2half_rn(hW[(size_t)n*512 + k]);
        return;
    } blk -= PB_WHM;
    if (blk < PB_WVOZ){
        // composite: Wvoz[256+n, k] = sum_d Wozh[n,d] * Wv[d,k]; bvoz[256+n] = bozh[n] + sum_d vb[d]*Wozh[n,d]
        int n = blk, k = threadIdx.x;
        float s = 0.f;
        for (int d = 0; d < 256; d++){
            float wz = (n < 256) ? zW[(size_t)n*512 + 256 + d]
                     : (n < 512) ? rW[(size_t)(n-256)*512 + 256 + d]
                                 : hW[(size_t)(n-512)*512 + 256 + d];
            s = fmaf(wz, vW[d*256 + k], s);
        }
        g_Wvoz[(size_t)(256 + n)*256 + k] = __float2half_rn(s);
        if (k == 0){
            float bq = (n < 256) ? zb[n] : (n < 512) ? rb[n-256] : hb[n-512];
            for (int d = 0; d < 256; d++){
                float wz = (n < 256) ? zW[(size_t)n*512 + 256 + d]
                         : (n < 512) ? rW[(size_t)(n-256)*512 + 256 + d]
                                     : hW[(size_t)(n-512)*512 + 256 + d];
                bq = fmaf(vb[d], wz, bq);
            }
            g_bvoz[256 + n] = bq;
        }
        return;
    } blk -= PB_WVOZ;
    if (blk < PB_WV){
        int i = blk*256 + threadIdx.x;
        g_Wvoz[i] = __float2half_rn(vW[i]);
        return;
    } blk -= PB_WV;
    if (blk < PB_MEMC){
        size_t base = ((size_t)blk*256 + threadIdx.x) * 8;
        float4 a = *reinterpret_cast<const float4*>(memory + base);
        float4 bq = *reinterpret_cast<const float4*>(memory + base + 4);
        __half2 o0 = __floats2half2_rn(a.x, a.y);
        __half2 o1 = __floats2half2_rn(a.z, a.w);
        __half2 o2 = __floats2half2_rn(bq.x, bq.y);
        __half2 o3 = __floats2half2_rn(bq.z, bq.w);
        uint4 pk;
        pk.x = *reinterpret_cast<uint32_t*>(&o0);
        pk.y = *reinterpret_cast<uint32_t*>(&o1);
        pk.z = *reinterpret_cast<uint32_t*>(&o2);
        pk.w = *reinterpret_cast<uint32_t*>(&o3);
        *reinterpret_cast<uint4*>(g_MEMh + base) = pk;
        return;
    } blk -= PB_MEMC;
    {
        int b = blk, t = threadIdx.x;
        float ot = O_t[(size_t)b*256 + t];
        float op = O_prev[(size_t)b*256 + t];
        float dl = ot - op;
        float s0 = ot*ot, s1 = op*op, s2 = dl*dl, s3 = ot*op;
        #pragma unroll
        for (int off = 16; off; off >>= 1){
            s0 += __shfl_xor_sync(0xffffffffu, s0, off);
            s1 += __shfl_xor_sync(0xffffffffu, s1, off);
            s2 += __shfl_xor_sync(0xffffffffu, s2, off);
            s3 += __shfl_xor_sync(0xffffffffu, s3, off);
        }
        __shared__ float4 ws[8];
        __shared__ float4 tot;
        int w = t >> 5;
        if ((t & 31) == 0) ws[w] = make_float4(s0, s1, s2, s3);
        __syncthreads();
        if (t == 0){
            float4 r = ws[0];
            #pragma unroll
            for (int i = 1; i < 8; i++){ r.x += ws[i].x; r.y += ws[i].y; r.z += ws[i].z; r.w += ws[i].w; }
            tot = r;
        }
        __syncthreads();
        float n_t = sqrtf(tot.x), n_p = sqrtf(tot.y), rd = sqrtf(tot.z);
        float ra  = tot.w / (n_t*n_p + 1e-6f);
        float wt  = 0.5f*(tanhf(n_t*wW[t*3+0] + rd*wW[t*3+1] + ra*wW[t*3+2] + wb[t]) + 1.f);
        out_Wt[(size_t)b*256 + t] = wt;
        g_X[(size_t)b*512 + t]       = __float2half_rn(op);
        g_X[(size_t)b*512 + 256 + t] = __float2half_rn(ot * wt);
    }
}

// ---------------- LSTM activations (half2-vectorized) ----------------
__global__ void k_lstm_act(){
    int i = blockIdx.x*256 + threadIdx.x;
    const __half2* G = reinterpret_cast<const __half2*>(g_gates);
    int b = i >> 7, d2 = i & 127;
    float2 ig = __half22float2(G[(size_t)b*384 + d2]);
    float2 gg = __half22float2(G[(size_t)b*384 + 128 + d2]);
    float2 og = __half22float2(G[(size_t)b*384 + 256 + d2]);
    float c0 = sigf(ig.x) * tanhf(gg.x);
    float c1 = sigf(ig.y) * tanhf(gg.y);
    reinterpret_cast<__half2*>(g_OTP)[i] =
        __floats2half2_rn(sigf(og.x)*tanhf(c0), sigf(og.y)*tanhf(c1));
}

// ---------------- attention v2: 1 warp per batch row, fp16 memory, no smem ----------------
__global__ void __launch_bounds__(256) k_attn(){
    int b = blockIdx.x*8 + (threadIdx.x >> 5);
    int lane = threadIdx.x & 31;

    uint4 qv = *reinterpret_cast<const uint4*>(g_QK + (size_t)b*256 + lane*8);
    float qf[8];
    {
        float2 t;
        t = __half22float2(*reinterpret_cast<__half2*>(&qv.x)); qf[0]=t.x; qf[1]=t.y;
        t = __half22float2(*reinterpret_cast<__half2*>(&qv.y)); qf[2]=t.x; qf[3]=t.y;
        t = __half22float2(*reinterpret_cast<__half2*>(&qv.z)); qf[4]=t.x; qf[5]=t.y;
        t = __half22float2(*reinterpret_cast<__half2*>(&qv.w)); qf[6]=t.x; qf[7]=t.y;
    }

    uint4 mv[ML_];
    float sc[ML_];
    const h16* mb = g_MEMh + (size_t)b*ML_*256;
    #pragma unroll
    for (int m = 0; m < ML_; m++){
        mv[m] = *reinterpret_cast<const uint4*>(mb + m*256 + lane*8);
        float s = 0.f;
        const __half2* hp = reinterpret_cast<const __half2*>(&mv[m]);
        #pragma unroll
        for (int q = 0; q < 4; q++){
            float2 f = __half22float2(hp[q]);
            s = fmaf(qf[2*q], f.x, s);
            s = fmaf(qf[2*q+1], f.y, s);
        }
        #pragma unroll
        for (int off = 16; off; off >>= 1) s += __shfl_xor_sync(0xffffffffu, s, off);
        sc[m] = s * 0.0625f;
    }
    float mx = sc[0];
    #pragma unroll
    for (int m = 1; m < ML_; m++) mx = fmaxf(mx, sc[m]);
    float e[ML_], ssum = 0.f;
    #pragma unroll
    for (int m = 0; m < ML_; m++){ e[m] = expf(sc[m] - mx); ssum += e[m]; }
    float inv = 1.f / ssum;

    float wm[8];
    #pragma unroll
    for (int q = 0; q < 8; q++) wm[q] = 0.f;
    #pragma unroll
    for (int m = 0; m < ML_; m++){
        float am = e[m] * inv;
        const __half2* hp = reinterpret_cast<const __half2*>(&mv[m]);
        #pragma unroll
        for (int q = 0; q < 4; q++){
            float2 f = __half22float2(hp[q]);
            wm[2*q]   = fmaf(am, f.x, wm[2*q]);
            wm[2*q+1] = fmaf(am, f.y, wm[2*q+1]);
        }
    }
    __half2 o0 = __floats2half2_rn(wm[0], wm[1]);
    __half2 o1 = __floats2half2_rn(wm[2], wm[3]);
    __half2 o2 = __floats2half2_rn(wm[4], wm[5]);
    __half2 o3 = __floats2half2_rn(wm[6], wm[7]);
    uint4 pk;
    pk.x = *reinterpret_cast<uint32_t*>(&o0);
    pk.y = *reinterpret_cast<uint32_t*>(&o1);
    pk.z = *reinterpret_cast<uint32_t*>(&o2);
    pk.w = *reinterpret_cast<uint32_t*>(&o3);
    *reinterpret_cast<uint4*>(g_WM + (size_t)b*256 + lane*8) = pk;
}

// ---------------- launcher ----------------
extern "C" void kernel_launch(void* const* d_in, const int* in_sizes, int n_in,
                              void* d_out, int out_size)
{
    const float* O_t     = (const float*)d_in[0];
    const float* O_prev  = (const float*)d_in[1];
    const float* memory  = (const float*)d_in[2];
    const float* w_mlp_W = (const float*)d_in[3];
    const float* w_mlp_b = (const float*)d_in[4];
    const float* lstm_Wih= (const float*)d_in[5];
    const float* lstm_bih= (const float*)d_in[7];
    const float* lstm_bhh= (const float*)d_in[8];
    const float* q_W = (const float*)d_in[9];   const float* q_b = (const float*)d_in[10];
    const float* k_W = (const float*)d_in[11];  // k_b cancels in softmax
    const float* v_W = (const float*)d_in[13];  const float* v_b = (const float*)d_in[14];
    const float* z_W = (const float*)d_in[15];  const float* z_b = (const float*)d_in[16];
    const float* r_W = (const float*)d_in[17];  const float* r_b = (const float*)d_in[18];
    const float* h_W = (const float*)d_in[19];  const float* h_b = (const float*)d_in[20];

    float* out      = (float*)d_out;
    float* out0     = out;
    float* out_mem  = out0 + (size_t)B_*D_;
    float* out2     = out_mem + (size_t)B_*ML_*D_;
    float* out3     = out2 + (size_t)B_*D_;

    cudaFuncSetAttribute(k_mma<5>, cudaFuncAttributeMaxDynamicSharedMemorySize, SMEM_TOTAL);
    cudaFuncSetAttribute(k_mma<6>, cudaFuncAttributeMaxDynamicSharedMemorySize, SMEM_TOTAL);
    cudaFuncSetAttribute(k_gru,    cudaFuncAttributeMaxDynamicSharedMemorySize, GRU_SMEM);

    float *pbigo,*pbvoz,*pbqk;
    h16 *pQK,*pGates,*pOZH,*pX,*pOTP,*pWM,*pMEMh;
    h16 *pWigo,*pWqk,*pWvoz,*pWzrm,*pWhm;
    cudaGetSymbolAddress((void**)&pQK,    g_QK);
    cudaGetSymbolAddress((void**)&pbigo,  g_bigo);
    cudaGetSymbolAddress((void**)&pbvoz,  g_bvoz);
    cudaGetSymbolAddress((void**)&pbqk,   g_bqk);
    cudaGetSymbolAddress((void**)&pGates, g_gates);
    cudaGetSymbolAddress((void**)&pOZH,   g_OZH);
    cudaGetSymbolAddress((void**)&pX,     g_X);
    cudaGetSymbolAddress((void**)&pOTP,   g_OTP);
    cudaGetSymbolAddress((void**)&pWM,    g_WM);
    cudaGetSymbolAddress((void**)&pMEMh,  g_MEMh);
    cudaGetSymbolAddress((void**)&pWigo,  g_Wigo);
    cudaGetSymbolAddress((void**)&pWqk,   g_Wqk);
    cudaGetSymbolAddress((void**)&pWvoz,  g_Wvoz);
    cudaGetSymbolAddress((void**)&pWzrm,  g_Wzrm);
    cudaGetSymbolAddress((void**)&pWhm,   g_Whm);

    // 1: fused front (weights + Wqk + Wvoz composite + biases + frame + mem->fp16)
    k_prep_all<<<PB_TOTAL, 256>>>(q_W, k_W, q_b, lstm_Wih, lstm_bih, lstm_bhh,
                                  v_W, v_b, z_W, r_W, h_W, z_b, r_b, h_b,
                                  memory, O_t, O_prev, w_mlp_W, w_mlp_b, out3);
    // 2: LSTM gates [B,768] fp16, K=512
    k_mma<5><<<dim3(6, B_/128), 256, SMEM_TOTAL>>>(
        pX, pWigo, pbigo, pGates, nullptr, nullptr, nullptr,
        B_, 768, 512);
    // 3: LSTM activations -> OTP (fp16)
    k_lstm_act<<<(B_*128)/256, 256>>>();
    // 4: QK = OTP @ Wqk^T + bqk  [B,256] fp16
    k_mma<5><<<dim3(2, B_/128), 256, SMEM_TOTAL>>>(
        pOTP, pWqk, pbqk, pQK, nullptr, nullptr, nullptr,
        B_, 256, 256);
    // 5: attention v2 -> WM (fp16)
    k_attn<<<B_/8, 256>>>();
    // 6: merged V/OZH GEMM [B,1024] from WM: cols<256 -> out0/out2/mem slot9, cols>=256 -> OZH
    k_mma<6><<<dim3(8, B_/128), 256, SMEM_TOTAL>>>(
        pWM, pWvoz, pbvoz, pOZH, out0, out_mem, out2,
        B_, 1024, 256);
    // 7: fused GRU v3
    k_gru<<<M2_/64, 256, GRU_SMEM>>>(pMEMh, pWzrm, pWhm, pOZH, out_mem);
}

// round 16
// speedup vs baseline: 1.0660x; 1.0660x over previous
#include <cuda_runtime.h>
#include <cuda_fp16.h>
#include <math.h>
#include <stdint.h>

#define B_   16384
#define D_   256
#define ML_  10
#define M2_  (B_*9)

typedef __half h16;

// ---------------- fp16 scratch ----------------
__device__ __align__(256) h16 g_QK   [(size_t)B_*256];
__device__ __align__(256) h16 g_gates[(size_t)B_*768];
__device__ __align__(256) h16 g_OZH  [(size_t)B_*768];
__device__ __align__(256) h16 g_X   [(size_t)B_*512];
__device__ __align__(256) h16 g_OTP [(size_t)B_*256];
__device__ __align__(256) h16 g_WM  [(size_t)B_*256];
__device__ __align__(256) h16 g_OUP [(size_t)B_*256];
// ---------------- fp16 weights ----------------
__device__ __align__(256) h16 g_Wigo [768*512];
__device__ __align__(256) h16 g_Wqk  [65536];
__device__ __align__(256) h16 g_Wv   [65536];
__device__ __align__(256) h16 g_Wzrm [512*256];
__device__ __align__(256) h16 g_Whm  [256*256];
__device__ __align__(256) h16 g_Wozh [768*256];
__device__ __align__(256) float g_bigo[768];
__device__ __align__(256) float g_bozh[768];
__device__ __align__(256) float g_bqk [256];

__device__ __forceinline__ float sigf(float x){ return 1.f/(1.f+expf(-x)); }

// ---------------- PTX helpers (base ISA only) ----------------
__device__ __forceinline__ uint32_t smem_u32(const void* p){
    uint32_t a; asm("{ .reg .u64 t; cvta.to.shared.u64 t, %1; cvt.u32.u64 %0, t; }" : "=r"(a) : "l"(p));
    return a;
}
__device__ __forceinline__ void ldsm4(uint32_t* r, uint32_t addr){
    asm volatile("ldmatrix.sync.aligned.m8n8.x4.shared.b16 {%0,%1,%2,%3}, [%4];"
        : "=r"(r[0]),"=r"(r[1]),"=r"(r[2]),"=r"(r[3]) : "r"(addr));
}
__device__ __forceinline__ void mma_f16(float* c, const uint32_t* a, const uint32_t* b){
    asm volatile("mma.sync.aligned.m16n8k16.row.col.f32.f16.f16.f32 "
        "{%0,%1,%2,%3}, {%4,%5,%6,%7}, {%8,%9}, {%0,%1,%2,%3};"
        : "+f"(c[0]),"+f"(c[1]),"+f"(c[2]),"+f"(c[3])
        : "r"(a[0]),"r"(a[1]),"r"(a[2]),"r"(a[3]), "r"(b[0]),"r"(b[1]));
}
__device__ __forceinline__ void cpa16(uint32_t dst, const void* src){
    asm volatile("cp.async.cg.shared.global [%0], [%1], 16;" :: "r"(dst), "l"(src));
}
#define CP_COMMIT() asm volatile("cp.async.commit_group;" ::: "memory")
#define CP_WAIT1()  asm volatile("cp.async.wait_group 1;"  ::: "memory")
#define CP_WAIT0()  asm volatile("cp.async.wait_group 0;"  ::: "memory")

#define ROWB     144
#define STAGE_SZ 36864
#define SMEM_TOTAL (3*STAGE_SZ)

// ================== fp16 HMMA GEMM: C[M,N] = A[M,K] @ W[N,K]^T ==================
// CTA 128x128, 8 warps (2x4), warp tile 64x32, K-chunk 64, 3-stage cp.async, 2 CTAs/SM.
// EPI 5: C16 fp16 = v + bias[col]
// EPI 2: V-mode: v+=bias; fp16(v) -> C16(=OUP); v -> out0, out2, out_mem slot 9
template<int EPI>
__global__ void __launch_bounds__(256,2) k_mma(
    const h16* __restrict__ A,
    const h16* __restrict__ W,
    const float* __restrict__ bias,
    h16* __restrict__ C16,
    float* __restrict__ out0, float* __restrict__ out_mem, float* __restrict__ out2,
    int M, int N, int K)
{
    extern __shared__ char smem[];
    uint32_t sb = smem_u32(smem);
    const int tid = threadIdx.x, lane = tid & 31, w = tid >> 5;
    const int wm = w >> 2, wn = w & 3;
    const int m0 = blockIdx.y * 128, n0 = blockIdx.x * 128;
    const int nch = K >> 6;

    float acc[4][4][4];
    #pragma unroll
    for (int i=0;i<4;i++)
        #pragma unroll
        for (int j=0;j<4;j++)
            #pragma unroll
            for (int k=0;k<4;k++) acc[i][j][k]=0.f;

    auto load_chunk = [&](int c, int s){
        uint32_t st = sb + s*STAGE_SZ;
        #pragma unroll
        for (int t=0;t<4;t++){
            int u = tid + t*256;
            int row = u >> 3, q = u & 7;
            cpa16(st + row*ROWB + q*16, A + (size_t)(m0+row)*K + c*64 + q*8);
        }
        #pragma unroll
        for (int t=0;t<4;t++){
            int u = tid + t*256;
            int row = u >> 3, q = u & 7;
            cpa16(st + 18432 + row*ROWB + q*16, W + (size_t)(n0+row)*K + c*64 + q*8);
        }
        CP_COMMIT();
    };

    load_chunk(0, 0);
    load_chunk(1, 1);

    for (int c = 0; c < nch; c++){
        if (c == nch - 1) CP_WAIT0(); else CP_WAIT1();
        __syncthreads();
        if (c + 2 < nch) load_chunk(c + 2, (c + 2) % 3);

        uint32_t sA = sb + (c % 3)*STAGE_SZ;
        uint32_t sW = sA + 18432;
        #pragma unroll
        for (int kk = 0; kk < 4; kk++){
            uint32_t a[4][4];
            #pragma unroll
            for (int i = 0; i < 4; i++){
                int rl = wm*64 + i*16 + (lane & 7) + ((lane & 8) ? 8 : 0);
                uint32_t colb = kk*32 + ((lane & 16) ? 16 : 0);
                ldsm4(a[i], sA + rl*ROWB + colb);
            }
            uint32_t bf[4][2];
            #pragma unroll
            for (int jp = 0; jp < 2; jp++){
                int nl = wn*32 + jp*16 + (lane & 7) + ((lane & 16) ? 8 : 0);
                uint32_t colb = kk*32 + ((lane & 8) ? 16 : 0);
                uint32_t t4[4];
                ldsm4(t4, sW + nl*ROWB + colb);
                bf[2*jp][0]=t4[0]; bf[2*jp][1]=t4[1]; bf[2*jp+1][0]=t4[2]; bf[2*jp+1][1]=t4[3];
            }
            #pragma unroll
            for (int i=0;i<4;i++)
                #pragma unroll
                for (int j=0;j<4;j++) mma_f16(acc[i][j], a[i], bf[j]);
        }
        __syncthreads();
    }

    #pragma unroll
    for (int j = 0; j < 4; j++){
        int col = n0 + wn*32 + j*8 + (lane & 3)*2;
        float b0 = bias ? bias[col]   : 0.f;
        float b1 = bias ? bias[col+1] : 0.f;
        #pragma unroll
        for (int i = 0; i < 4; i++){
            int row = m0 + wm*64 + i*16 + (lane >> 2);
            #pragma unroll
            for (int h = 0; h < 2; h++){
                int rr = row + h*8;
                float v0 = acc[i][j][2*h+0] + b0;
                float v1 = acc[i][j][2*h+1] + b1;
                if (EPI == 5){
                    *reinterpret_cast<__half2*>(C16 + (size_t)rr*N + col) = __floats2half2_rn(v0, v1);
                } else {  // EPI 2
                    size_t o = (size_t)rr*256 + col;
                    float2 fv = make_float2(v0, v1);
                    *reinterpret_cast<__half2*>(C16 + o) = __floats2half2_rn(v0, v1);
                    *reinterpret_cast<float2*>(out0 + o) = fv;
                    *reinterpret_cast<float2*>(out2 + o) = fv;
                    *reinterpret_cast<float2*>(out_mem + (size_t)rr*(ML_*256) + 9*256 + col) = fv;
                }
            }
        }
    }
}

// ================== fused GRU v4: 64-row CTAs, 2 CTAs/SM, fp32 A-source ==================
#define GRU_ROWSTR 528
#define GRU_A_OFF  0
#define GRU_RM_OFF 33792
#define GRU_ZS_OFF 67584
#define GRU_W_OFF  83968
#define GRU_WSTG   10240
#define GRU_SMEM   104448

__device__ __forceinline__ uint32_t zswz(int rl, int ccl){
    return (uint32_t)((rl*256 + ccl*2) ^ ((rl & 7) << 4));
}

__global__ void __launch_bounds__(256,2) k_gru(
    const float* __restrict__ memory,
    const h16* __restrict__ Wzrm, const h16* __restrict__ Whm,
    const h16* __restrict__ ozh,
    float* __restrict__ out_mem)
{
    extern __shared__ char smem[];
    uint32_t sb = smem_u32(smem);
    const int tid = threadIdx.x, lane = tid & 31, w = tid >> 5;
    const int wm = w >> 2, wn = w & 3;
    const int m0 = blockIdx.x * 64;

    // load 64 memory rows: fp32 LDG -> fp16 cvt -> SMEM (same rounding as before)
    #pragma unroll
    for (int t = 0; t < 8; t++){
        int u = tid + t*256;
        int row = u >> 5, q = u & 31;
        int rr = m0 + row, b = rr/9, m = rr - b*9 + 1;
        const float* src = memory + ((size_t)b*10 + m)*256 + q*8;
        float4 a = *reinterpret_cast<const float4*>(src);
        float4 c = *reinterpret_cast<const float4*>(src + 4);
        __half2 o0 = __floats2half2_rn(a.x, a.y);
        __half2 o1 = __floats2half2_rn(a.z, a.w);
        __half2 o2 = __floats2half2_rn(c.x, c.y);
        __half2 o3 = __floats2half2_rn(c.z, c.w);
        uint4 pk;
        pk.x = *reinterpret_cast<uint32_t*>(&o0);
        pk.y = *reinterpret_cast<uint32_t*>(&o1);
        pk.z = *reinterpret_cast<uint32_t*>(&o2);
        pk.w = *reinterpret_cast<uint32_t*>(&o3);
        *reinterpret_cast<uint4*>(smem + GRU_A_OFF + row*GRU_ROWSTR + q*16) = pk;
    }
    __syncthreads();

    auto wptr = [&](int p)->const h16*{
        switch(p){
            case 0: return Wzrm;
            case 1: return Wzrm + 256*256;
            case 2: return Wzrm + 384*256;
            case 3: return Whm;
            case 4: return Wzrm + 128*256;
            default:return Whm + 128*256;
        }
    };
    auto wload = [&](const h16* Wg, int c, int s){
        #pragma unroll
        for (int t = 0; t < 2; t++){
            int u = tid + t*256;
            int row = u >> 2, q = u & 3;
            cpa16(sb + GRU_W_OFF + s*GRU_WSTG + row*80 + q*16,
                  Wg + (size_t)row*256 + c*32 + q*8);
        }
        CP_COMMIT();
    };

    wload(wptr(0), 0, 0);
    wload(wptr(0), 1, 1);

    for (int pass = 0; pass < 6; pass++){
        const h16* Wg;
        uint32_t aOff; int colOff, mode;
        switch(pass){
            case 0: Wg=wptr(0); aOff=GRU_A_OFF;  colOff=0;   mode=0; break;
            case 1: Wg=wptr(1); aOff=GRU_A_OFF;  colOff=0;   mode=1; break;
            case 2: Wg=wptr(2); aOff=GRU_A_OFF;  colOff=128; mode=1; break;
            case 3: Wg=wptr(3); aOff=GRU_RM_OFF; colOff=0;   mode=2; break;
            case 4: Wg=wptr(4); aOff=GRU_A_OFF;  colOff=128; mode=0; break;
            default:Wg=wptr(5); aOff=GRU_RM_OFF; colOff=128; mode=2; break;
        }
        uint32_t aBase = sb + aOff;

        float acc[2][4][4];
        #pragma unroll
        for (int i=0;i<2;i++)
            #pragma unroll
            for (int j=0;j<4;j++)
                #pragma unroll
                for (int k=0;k<4;k++) acc[i][j][k]=0.f;

        for (int c = 0; c < 8; c++){
            if (c == 7) CP_WAIT0(); else CP_WAIT1();
            __syncthreads();
            uint32_t sW = sb + GRU_W_OFF + (c & 1)*GRU_WSTG;
            #pragma unroll
            for (int s = 0; s < 2; s++){
                int kg = c*2 + s;
                uint32_t a[2][4];
                #pragma unroll
                for (int i = 0; i < 2; i++){
                    int rl = wm*32 + i*16 + (lane & 7) + ((lane & 8) ? 8 : 0);
                    uint32_t colb = kg*32 + ((lane & 16) ? 16 : 0);
                    ldsm4(a[i], aBase + rl*GRU_ROWSTR + colb);
                }
                uint32_t bf[4][2];
                #pragma unroll
                for (int jp = 0; jp < 2; jp++){
                    int nl = wn*32 + jp*16 + (lane & 7) + ((lane & 16) ? 8 : 0);
                    uint32_t colb = s*32 + ((lane & 8) ? 16 : 0);
                    uint32_t t4[4];
                    ldsm4(t4, sW + nl*80 + colb);
                    bf[2*jp][0]=t4[0]; bf[2*jp][1]=t4[1]; bf[2*jp+1][0]=t4[2]; bf[2*jp+1][1]=t4[3];
                }
                #pragma unroll
                for (int i=0;i<2;i++)
                    #pragma unroll
                    for (int j=0;j<4;j++) mma_f16(acc[i][j], a[i], bf[j]);
            }
            __syncthreads();
            if (c + 2 < 8) wload(Wg, c + 2, c & 1);
        }

        if (pass < 5){
            const h16* Wn = wptr(pass + 1);
            wload(Wn, 0, 0);
            wload(Wn, 1, 1);
        }

        #pragma unroll
        for (int j = 0; j < 4; j++){
            int ccl = wn*32 + j*8 + (lane & 3)*2;
            int cc  = colOff + ccl;
            #pragma unroll
            for (int i = 0; i < 2; i++){
                #pragma unroll
                for (int h = 0; h < 2; h++){
                    int rl = wm*32 + i*16 + (lane >> 2) + h*8;
                    int rr = m0 + rl, b = rr/9;
                    float v0 = acc[i][j][2*h], v1 = acc[i][j][2*h+1];
                    if (mode == 0){
                        float2 oz = __half22float2(*reinterpret_cast<const __half2*>(ozh + (size_t)b*768 + cc));
                        *reinterpret_cast<__half2*>(smem + GRU_ZS_OFF + zswz(rl, ccl)) =
                            __floats2half2_rn(sigf(v0+oz.x), sigf(v1+oz.y));
                    } else if (mode == 1){
                        float2 oz = __half22float2(*reinterpret_cast<const __half2*>(ozh + (size_t)b*768 + 256 + cc));
                        float2 mv = __half22float2(*reinterpret_cast<const __half2*>(smem + GRU_A_OFF + rl*GRU_ROWSTR + cc*2));
                        *reinterpret_cast<__half2*>(smem + GRU_RM_OFF + rl*GRU_ROWSTR + cc*2) =
                            __floats2half2_rn(sigf(v0+oz.x)*mv.x, sigf(v1+oz.y)*mv.y);
                    } else {
                        int m = rr - b*9 + 1;
                        float2 oz = __half22float2(*reinterpret_cast<const __half2*>(ozh + (size_t)b*768 + 512 + cc));
                        float mt0 = tanhf(v0+oz.x), mt1 = tanhf(v1+oz.y);
                        float2 zv = __half22float2(*reinterpret_cast<const __half2*>(smem + GRU_ZS_OFF + zswz(rl, ccl)));
                        float2 mv = __half22float2(*reinterpret_cast<const __half2*>(smem + GRU_A_OFF + rl*GRU_ROWSTR + cc*2));
                        *reinterpret_cast<float2*>(out_mem + (size_t)b*(ML_*256) + (size_t)(m-1)*256 + cc) =
                            make_float2(zv.x*mv.x + (1.f-zv.x)*mt0, zv.y*mv.y + (1.f-zv.y)*mt1);
                    }
                }
            }
        }
        __syncthreads();
    }
}

// ---------------- fused front launch: weights + Wqk + biases + frame ----------------
#define PB_QK    256
#define PB_BIAS  6
#define PB_WIGO  1536
#define PB_WZRM  512
#define PB_WHM   256
#define PB_WOZH  768
#define PB_WV    256
#define PB_FRAME 16384
#define PB_TOTAL (PB_QK+PB_BIAS+PB_WIGO+PB_WZRM+PB_WHM+PB_WOZH+PB_WV+PB_FRAME)

__global__ void k_prep_all(const float* __restrict__ qW, const float* __restrict__ kW,
                           const float* __restrict__ qb,
                           const float* __restrict__ Wih,
                           const float* __restrict__ bih, const float* __restrict__ bhh,
                           const float* __restrict__ vW,
                           const float* __restrict__ zW, const float* __restrict__ rW,
                           const float* __restrict__ hW,
                           const float* __restrict__ zb, const float* __restrict__ rb,
                           const float* __restrict__ hb,
                           const float* __restrict__ O_t, const float* __restrict__ O_prev,
                           const float* __restrict__ wW, const float* __restrict__ wb,
                           float* __restrict__ out_Wt)
{
    int blk = blockIdx.x;
    if (blk < PB_QK){
        int j = blk, e = threadIdx.x;
        float s = 0.f;
        for (int d = 0; d < 256; d++) s = fmaf(qW[d*256 + e], kW[d*256 + j], s);
        g_Wqk[j*256 + e] = __float2half_rn(s);
        if (e == 0){
            float bq = 0.f;
            for (int d = 0; d < 256; d++) bq = fmaf(qb[d], kW[d*256 + j], bq);
            g_bqk[j] = bq;
        }
        return;
    } blk -= PB_QK;
    if (blk < PB_BIAS){
        int i = blk*256 + threadIdx.x;
        if (i < 768){
            int src = (i < 256) ? i : i + 256;
            g_bigo[i] = bih[src] + bhh[src];
        } else if (i < 1536){
            int n = i - 768;
            g_bozh[n] = (n < 256) ? zb[n] : (n < 512) ? rb[n-256] : hb[n-512];
        }
        return;
    } blk -= PB_BIAS;
    if (blk < PB_WIGO){
        int i = blk*256 + threadIdx.x;
        int n = i >> 9, k = i & 511;
        int src = (n < 256) ? n : n + 256;
        g_Wigo[i] = __float2half_rn(Wih[(size_t)src*512 + k]);
        return;
    } blk -= PB_WIGO;
    if (blk < PB_WZRM){
        int i = blk*256 + threadIdx.x;
        int n = i >> 8, k = i & 255;
        float v = (n < 256) ? zW[(size_t)n*512 + k] : rW[(size_t)(n-256)*512 + k];
        g_Wzrm[i] = __float2half_rn(v);
        return;
    } blk -= PB_WZRM;
    if (blk < PB_WHM){
        int i = blk*256 + threadIdx.x;
        int n = i >> 8, k = i & 255;
        g_Whm[i] = __float2half_rn(hW[(size_t)n*512 + k]);
        return;
    } blk -= PB_WHM;
    if (blk < PB_WOZH){
        int i = blk*256 + threadIdx.x;
        int n = i >> 8, k = i & 255;
        float v = (n < 256) ? zW[(size_t)n*512 + 256 + k]
                : (n < 512) ? rW[(size_t)(n-256)*512 + 256 + k]
                            : hW[(size_t)(n-512)*512 + 256 + k];
        g_Wozh[i] = __float2half_rn(v);
        return;
    } blk -= PB_WOZH;
    if (blk < PB_WV){
        int i = blk*256 + threadIdx.x;
        g_Wv[i] = __float2half_rn(vW[i]);
        return;
    } blk -= PB_WV;
    {
        // frame weighting
        int b = blk, t = threadIdx.x;
        float ot = O_t[(size_t)b*256 + t];
        float op = O_prev[(size_t)b*256 + t];
        float dl = ot - op;
        float s0 = ot*ot, s1 = op*op, s2 = dl*dl, s3 = ot*op;
        #pragma unroll
        for (int off = 16; off; off >>= 1){
            s0 += __shfl_xor_sync(0xffffffffu, s0, off);
            s1 += __shfl_xor_sync(0xffffffffu, s1, off);
            s2 += __shfl_xor_sync(0xffffffffu, s2, off);
            s3 += __shfl_xor_sync(0xffffffffu, s3, off);
        }
        __shared__ float4 ws[8];
        __shared__ float4 tot;
        int w = t >> 5;
        if ((t & 31) == 0) ws[w] = make_float4(s0, s1, s2, s3);
        __syncthreads();
        if (t == 0){
            float4 r = ws[0];
            #pragma unroll
            for (int i = 1; i < 8; i++){ r.x += ws[i].x; r.y += ws[i].y; r.z += ws[i].z; r.w += ws[i].w; }
            tot = r;
        }
        __syncthreads();
        float n_t = sqrtf(tot.x), n_p = sqrtf(tot.y), rd = sqrtf(tot.z);
        float ra  = tot.w / (n_t*n_p + 1e-6f);
        float wt  = 0.5f*(tanhf(n_t*wW[t*3+0] + rd*wW[t*3+1] + ra*wW[t*3+2] + wb[t]) + 1.f);
        out_Wt[(size_t)b*256 + t] = wt;
        g_X[(size_t)b*512 + t]       = __float2half_rn(op);
        g_X[(size_t)b*512 + 256 + t] = __float2half_rn(ot * wt);
    }
}

// ---------------- LSTM activations (half2-vectorized) ----------------
__global__ void k_lstm_act(){
    int i = blockIdx.x*256 + threadIdx.x;
    const __half2* G = reinterpret_cast<const __half2*>(g_gates);
    int b = i >> 7, d2 = i & 127;
    float2 ig = __half22float2(G[(size_t)b*384 + d2]);
    float2 gg = __half22float2(G[(size_t)b*384 + 128 + d2]);
    float2 og = __half22float2(G[(size_t)b*384 + 256 + d2]);
    float c0 = sigf(ig.x) * tanhf(gg.x);
    float c1 = sigf(ig.y) * tanhf(gg.y);
    reinterpret_cast<__half2*>(g_OTP)[i] =
        __floats2half2_rn(sigf(og.x)*tanhf(c0), sigf(og.y)*tanhf(c1));
}

// ---------------- attention v3: 1 warp per batch row, fp32 memory source ----------------
__global__ void __launch_bounds__(256) k_attn(const float* __restrict__ memory){
    int b = blockIdx.x*8 + (threadIdx.x >> 5);
    int lane = threadIdx.x & 31;

    uint4 qv = *reinterpret_cast<const uint4*>(g_QK + (size_t)b*256 + lane*8);
    float qf[8];
    {
        float2 t;
        t = __half22float2(*reinterpret_cast<__half2*>(&qv.x)); qf[0]=t.x; qf[1]=t.y;
        t = __half22float2(*reinterpret_cast<__half2*>(&qv.y)); qf[2]=t.x; qf[3]=t.y;
        t = __half22float2(*reinterpret_cast<__half2*>(&qv.z)); qf[4]=t.x; qf[5]=t.y;
        t = __half22float2(*reinterpret_cast<__half2*>(&qv.w)); qf[6]=t.x; qf[7]=t.y;
    }

    float mv[ML_][8];
    float sc[ML_];
    const float* mb = memory + (size_t)b*ML_*256;
    #pragma unroll
    for (int m = 0; m < ML_; m++){
        float4 a = *reinterpret_cast<const float4*>(mb + m*256 + lane*8);
        float4 c = *reinterpret_cast<const float4*>(mb + m*256 + lane*8 + 4);
        mv[m][0]=a.x; mv[m][1]=a.y; mv[m][2]=a.z; mv[m][3]=a.w;
        mv[m][4]=c.x; mv[m][5]=c.y; mv[m][6]=c.z; mv[m][7]=c.w;
        float s = 0.f;
        #pragma unroll
        for (int q = 0; q < 8; q++) s = fmaf(qf[q], mv[m][q], s);
        #pragma unroll
        for (int off = 16; off; off >>= 1) s += __shfl_xor_sync(0xffffffffu, s, off);
        sc[m] = s * 0.0625f;
    }
    float mx = sc[0];
    #pragma unroll
    for (int m = 1; m < ML_; m++) mx = fmaxf(mx, sc[m]);
    float e[ML_], ssum = 0.f;
    #pragma unroll
    for (int m = 0; m < ML_; m++){ e[m] = expf(sc[m] - mx); ssum += e[m]; }
    float inv = 1.f / ssum;

    float wm[8];
    #pragma unroll
    for (int q = 0; q < 8; q++) wm[q] = 0.f;
    #pragma unroll
    for (int m = 0; m < ML_; m++){
        float am = e[m] * inv;
        #pragma unroll
        for (int q = 0; q < 8; q++) wm[q] = fmaf(am, mv[m][q], wm[q]);
    }
    __half2 o0 = __floats2half2_rn(wm[0], wm[1]);
    __half2 o1 = __floats2half2_rn(wm[2], wm[3]);
    __half2 o2 = __floats2half2_rn(wm[4], wm[5]);
    __half2 o3 = __floats2half2_rn(wm[6], wm[7]);
    uint4 pk;
    pk.x = *reinterpret_cast<uint32_t*>(&o0);
    pk.y = *reinterpret_cast<uint32_t*>(&o1);
    pk.z = *reinterpret_cast<uint32_t*>(&o2);
    pk.w = *reinterpret_cast<uint32_t*>(&o3);
    *reinterpret_cast<uint4*>(g_WM + (size_t)b*256 + lane*8) = pk;
}

// ---------------- launcher ----------------
extern "C" void kernel_launch(void* const* d_in, const int* in_sizes, int n_in,
                              void* d_out, int out_size)
{
    const float* O_t     = (const float*)d_in[0];
    const float* O_prev  = (const float*)d_in[1];
    const float* memory  = (const float*)d_in[2];
    const float* w_mlp_W = (const float*)d_in[3];
    const float* w_mlp_b = (const float*)d_in[4];
    const float* lstm_Wih= (const float*)d_in[5];
    const float* lstm_bih= (const float*)d_in[7];
    const float* lstm_bhh= (const float*)d_in[8];
    const float* q_W = (const float*)d_in[9];   const float* q_b = (const float*)d_in[10];
    const float* k_W = (const float*)d_in[11];  // k_b cancels in softmax
    const float* v_W = (const float*)d_in[13];  const float* v_b = (const float*)d_in[14];
    const float* z_W = (const float*)d_in[15];  const float* z_b = (const float*)d_in[16];
    const float* r_W = (const float*)d_in[17];  const float* r_b = (const float*)d_in[18];
    const float* h_W = (const float*)d_in[19];  const float* h_b = (const float*)d_in[20];

    float* out      = (float*)d_out;
    float* out0     = out;
    float* out_mem  = out0 + (size_t)B_*D_;
    float* out2     = out_mem + (size_t)B_*ML_*D_;
    float* out3     = out2 + (size_t)B_*D_;

    cudaFuncSetAttribute(k_mma<5>, cudaFuncAttributeMaxDynamicSharedMemorySize, SMEM_TOTAL);
    cudaFuncSetAttribute(k_mma<2>, cudaFuncAttributeMaxDynamicSharedMemorySize, SMEM_TOTAL);
    cudaFuncSetAttribute(k_gru,    cudaFuncAttributeMaxDynamicSharedMemorySize, GRU_SMEM);

    float *pbigo,*pbozh,*pbqk;
    h16 *pQK,*pGates,*pOZH,*pX,*pOTP,*pWM,*pOUP;
    h16 *pWigo,*pWqk,*pWv,*pWzrm,*pWhm,*pWozh;
    cudaGetSymbolAddress((void**)&pQK,    g_QK);
    cudaGetSymbolAddress((void**)&pbigo,  g_bigo);
    cudaGetSymbolAddress((void**)&pbozh,  g_bozh);
    cudaGetSymbolAddress((void**)&pbqk,   g_bqk);
    cudaGetSymbolAddress((void**)&pGates, g_gates);
    cudaGetSymbolAddress((void**)&pOZH,   g_OZH);
    cudaGetSymbolAddress((void**)&pX,     g_X);
    cudaGetSymbolAddress((void**)&pOTP,   g_OTP);
    cudaGetSymbolAddress((void**)&pWM,    g_WM);
    cudaGetSymbolAddress((void**)&pOUP,   g_OUP);
    cudaGetSymbolAddress((void**)&pWigo,  g_Wigo);
    cudaGetSymbolAddress((void**)&pWqk,   g_Wqk);
    cudaGetSymbolAddress((void**)&pWv,    g_Wv);
    cudaGetSymbolAddress((void**)&pWzrm,  g_Wzrm);
    cudaGetSymbolAddress((void**)&pWhm,   g_Whm);
    cudaGetSymbolAddress((void**)&pWozh,  g_Wozh);

    // 1: fused front (weights + Wqk + biases + frame) — no memconvert
    k_prep_all<<<PB_TOTAL, 256>>>(q_W, k_W, q_b, lstm_Wih, lstm_bih, lstm_bhh,
                                  v_W, z_W, r_W, h_W, z_b, r_b, h_b,
                                  O_t, O_prev, w_mlp_W, w_mlp_b, out3);
    // 2: LSTM gates [B,768] fp16, K=512
    k_mma<5><<<dim3(6, B_/128), 256, SMEM_TOTAL>>>(
        pX, pWigo, pbigo, pGates, nullptr, nullptr, nullptr,
        B_, 768, 512);
    // 3: LSTM activations -> OTP (fp16)
    k_lstm_act<<<(B_*128)/256, 256>>>();
    // 4: QK = OTP @ Wqk^T + bqk  [B,256] fp16
    k_mma<5><<<dim3(2, B_/128), 256, SMEM_TOTAL>>>(
        pOTP, pWqk, pbqk, pQK, nullptr, nullptr, nullptr,
        B_, 256, 256);
    // 5: attention v3 (fp32 memory source) -> WM (fp16)
    k_attn<<<B_/8, 256>>>(memory);
    // 6: V GEMM -> OUP (fp16) + out0/out2/mem slot 9 (fp32)
    k_mma<2><<<dim3(2, B_/128), 256, SMEM_TOTAL>>>(
        pWM, pWv, v_b, pOUP, out0, out_mem, out2,
        B_, 256, 256);
    // 7: OZH = O_up @ Wozh^T + bozh  [B,768] fp16
    k_mma<5><<<dim3(6, B_/128), 256, SMEM_TOTAL>>>(
        pOUP, pWozh, pbozh, pOZH, nullptr, nullptr, nullptr,
        B_, 768, 256);
    // 8: fused GRU v4 (fp32 memory A-source, in-loader cvt)
    k_gru<<<M2_/64, 256, GRU_SMEM>>>(memory, pWzrm, pWhm, pOZH, out_mem);
}